// round 1
// baseline (speedup 1.0000x reference)
#include <cuda_runtime.h>
#include <math.h>

// Problem constants
#define BB   2
#define CC   512
#define SS   8192
#define NHW  1024

#define SQRT_C   22.627416997969522f   // sqrt(512)
#define INV_SQRT_C 0.04419417382415922f

// Scratch (static __device__ globals — allocation-free contract)
__device__ float g_hn[(size_t)BB * CC * SS];            // [b][c][s]
__device__ float g_q [(size_t)BB * CC * SS];            // [b][c][s]
__device__ float g_k [(size_t)BB * CC * SS];            // [b][c][s]
__device__ float g_v [(size_t)BB * CC * SS];            // [b][c][s]
__device__ float g_p [(size_t)BB * SS * SS];            // [b][sq][sk] scores -> probs
__device__ float g_o [(size_t)BB * SS * CC];            // [b][s][c]

// ---------------------------------------------------------------------------
// RMS norm over channel dim: hn = x / max(||x||_c, 1e-12) * sqrt(C) * gamma[c]
// ---------------------------------------------------------------------------
__global__ void rms_kernel(const float* __restrict__ x,
                           const float* __restrict__ gamma) {
    int s = blockIdx.x * blockDim.x + threadIdx.x;
    int b = blockIdx.y;
    const float* xb = x + (size_t)b * CC * SS + s;
    float ss = 0.f;
#pragma unroll 8
    for (int c = 0; c < CC; c++) {
        float v = xb[(size_t)c * SS];
        ss += v * v;
    }
    float scale = SQRT_C / fmaxf(sqrtf(ss), 1e-12f);
    float* hb = g_hn + (size_t)b * CC * SS + s;
#pragma unroll 8
    for (int c = 0; c < CC; c++) {
        hb[(size_t)c * SS] = xb[(size_t)c * SS] * scale * gamma[c];
    }
}

// ---------------------------------------------------------------------------
// QKV projection: out[co][s] = sum_ci W[co][ci] * hn[ci][s] + bias[co]
// blockIdx.z = b*3 + which
// ---------------------------------------------------------------------------
__global__ void __launch_bounds__(256) qkv_kernel(
    const float* __restrict__ wq, const float* __restrict__ bq,
    const float* __restrict__ wk, const float* __restrict__ bk,
    const float* __restrict__ wv, const float* __restrict__ bv) {

    int which = blockIdx.z % 3;
    int b     = blockIdx.z / 3;
    const float* W    = which == 0 ? wq : (which == 1 ? wk : wv);
    const float* bias = which == 0 ? bq : (which == 1 ? bk : bv);
    float* Cout = (which == 0 ? g_q : (which == 1 ? g_k : g_v)) + (size_t)b * CC * SS;
    const float* Bm = g_hn + (size_t)b * CC * SS;

    int m0 = blockIdx.y * 128;   // co
    int n0 = blockIdx.x * 128;   // s

    __shared__ float As[16][128];
    __shared__ float Bs[16][128];

    int tid = threadIdx.x;
    int tx = tid % 16, ty = tid / 16;

    float acc[8][8];
#pragma unroll
    for (int i = 0; i < 8; i++)
#pragma unroll
        for (int j = 0; j < 8; j++) acc[i][j] = 0.f;

    for (int k0 = 0; k0 < CC; k0 += 16) {
        // A tile: W[m0+r][k0+cb..], transpose into As[k][m]
        {
            int r = tid / 2, cb = (tid % 2) * 8;
            const float4* p = (const float4*)(W + (size_t)(m0 + r) * CC + k0 + cb);
            float4 a0 = p[0], a1 = p[1];
            As[cb + 0][r] = a0.x; As[cb + 1][r] = a0.y; As[cb + 2][r] = a0.z; As[cb + 3][r] = a0.w;
            As[cb + 4][r] = a1.x; As[cb + 5][r] = a1.y; As[cb + 6][r] = a1.z; As[cb + 7][r] = a1.w;
        }
        // B tile: hn[k0+kr][n0 + nc..], direct
        {
            int kr = tid / 16, nc = (tid % 16) * 8;
            const float4* p = (const float4*)(Bm + (size_t)(k0 + kr) * SS + n0 + nc);
            float4 b0 = p[0], b1 = p[1];
            *(float4*)&Bs[kr][nc]     = b0;
            *(float4*)&Bs[kr][nc + 4] = b1;
        }
        __syncthreads();
#pragma unroll
        for (int kk = 0; kk < 16; kk++) {
            float a[8], bb[8];
#pragma unroll
            for (int i = 0; i < 8; i++) a[i]  = As[kk][ty * 8 + i];
#pragma unroll
            for (int j = 0; j < 8; j++) bb[j] = Bs[kk][tx * 8 + j];
#pragma unroll
            for (int i = 0; i < 8; i++)
#pragma unroll
                for (int j = 0; j < 8; j++) acc[i][j] += a[i] * bb[j];
        }
        __syncthreads();
    }

#pragma unroll
    for (int i = 0; i < 8; i++) {
        float bi = bias[m0 + ty * 8 + i];
#pragma unroll
        for (int j = 0; j < 8; j++)
            Cout[(size_t)(m0 + ty * 8 + i) * SS + n0 + tx * 8 + j] = acc[i][j] + bi;
    }
}

// ---------------------------------------------------------------------------
// Scores: p[sq][sk] = (sum_c q[c][sq]*k[c][sk]) / sqrt(C), allowed tiles only
// ---------------------------------------------------------------------------
__global__ void __launch_bounds__(256) qk_kernel() {
    int b  = blockIdx.z;
    int m0 = blockIdx.y * 128;   // sq
    int n0 = blockIdx.x * 128;   // sk
    if (n0 / NHW > m0 / NHW) return;   // masked tile: frame(sk) > frame(sq)

    const float* Q = g_q + (size_t)b * CC * SS;
    const float* K = g_k + (size_t)b * CC * SS;

    __shared__ float As[16][128];
    __shared__ float Bs[16][128];

    int tid = threadIdx.x;
    int tx = tid % 16, ty = tid / 16;

    float acc[8][8];
#pragma unroll
    for (int i = 0; i < 8; i++)
#pragma unroll
        for (int j = 0; j < 8; j++) acc[i][j] = 0.f;

    for (int k0 = 0; k0 < CC; k0 += 16) {
        int kr = tid / 16, nc = (tid % 16) * 8;
        {
            const float4* p = (const float4*)(Q + (size_t)(k0 + kr) * SS + m0 + nc);
            float4 a0 = p[0], a1 = p[1];
            *(float4*)&As[kr][nc]     = a0;
            *(float4*)&As[kr][nc + 4] = a1;
        }
        {
            const float4* p = (const float4*)(K + (size_t)(k0 + kr) * SS + n0 + nc);
            float4 b0 = p[0], b1 = p[1];
            *(float4*)&Bs[kr][nc]     = b0;
            *(float4*)&Bs[kr][nc + 4] = b1;
        }
        __syncthreads();
#pragma unroll
        for (int kk = 0; kk < 16; kk++) {
            float a[8], bb[8];
#pragma unroll
            for (int i = 0; i < 8; i++) a[i]  = As[kk][ty * 8 + i];
#pragma unroll
            for (int j = 0; j < 8; j++) bb[j] = Bs[kk][tx * 8 + j];
#pragma unroll
            for (int i = 0; i < 8; i++)
#pragma unroll
                for (int j = 0; j < 8; j++) acc[i][j] += a[i] * bb[j];
        }
        __syncthreads();
    }

    float* P = g_p + (size_t)b * SS * SS;
#pragma unroll
    for (int i = 0; i < 8; i++)
#pragma unroll
        for (int j = 0; j < 8; j++)
            P[(size_t)(m0 + ty * 8 + i) * SS + n0 + tx * 8 + j] = acc[i][j] * INV_SQRT_C;
}

// ---------------------------------------------------------------------------
// Row softmax, row limit L = (frame(sq)+1)*NHW
// ---------------------------------------------------------------------------
__global__ void softmax_kernel() {
    int sq = blockIdx.x;
    int b  = blockIdx.y;
    float* row = g_p + ((size_t)b * SS + sq) * SS;
    int L = (sq / NHW + 1) * NHW;
    int tid = threadIdx.x;

    __shared__ float red[256];

    float m = -1e30f;
    for (int t = tid; t < L; t += 256) m = fmaxf(m, row[t]);
    red[tid] = m; __syncthreads();
    for (int o = 128; o > 0; o >>= 1) {
        if (tid < o) red[tid] = fmaxf(red[tid], red[tid + o]);
        __syncthreads();
    }
    float M = red[0];
    __syncthreads();

    float s = 0.f;
    for (int t = tid; t < L; t += 256) {
        float e = __expf(row[t] - M);
        row[t] = e;
        s += e;
    }
    red[tid] = s; __syncthreads();
    for (int o = 128; o > 0; o >>= 1) {
        if (tid < o) red[tid] += red[tid + o];
        __syncthreads();
    }
    float inv = 1.f / red[0];
    for (int t = tid; t < L; t += 256) row[t] *= inv;
}

// ---------------------------------------------------------------------------
// PV: o[sq][c] = sum_{sk<L} p[sq][sk] * v[c][sk]
// ---------------------------------------------------------------------------
__global__ void __launch_bounds__(256) pv_kernel() {
    int b  = blockIdx.z;
    int m0 = blockIdx.y * 128;   // sq
    int n0 = blockIdx.x * 128;   // c
    int L  = (m0 / NHW + 1) * NHW;

    const float* P = g_p + (size_t)b * SS * SS;
    const float* V = g_v + (size_t)b * CC * SS;

    __shared__ float As[16][128];
    __shared__ float Bs[16][128];

    int tid = threadIdx.x;
    int tx = tid % 16, ty = tid / 16;

    float acc[8][8];
#pragma unroll
    for (int i = 0; i < 8; i++)
#pragma unroll
        for (int j = 0; j < 8; j++) acc[i][j] = 0.f;

    for (int k0 = 0; k0 < L; k0 += 16) {
        int r = tid / 2, cb = (tid % 2) * 8;
        {   // A tile: P[m0+r][k0+cb..] -> As[k][m] (transpose)
            const float4* p = (const float4*)(P + (size_t)(m0 + r) * SS + k0 + cb);
            float4 a0 = p[0], a1 = p[1];
            As[cb + 0][r] = a0.x; As[cb + 1][r] = a0.y; As[cb + 2][r] = a0.z; As[cb + 3][r] = a0.w;
            As[cb + 4][r] = a1.x; As[cb + 5][r] = a1.y; As[cb + 6][r] = a1.z; As[cb + 7][r] = a1.w;
        }
        {   // B tile: V[n0+r][k0+cb..] -> Bs[k][n] (transpose)
            const float4* p = (const float4*)(V + (size_t)(n0 + r) * SS + k0 + cb);
            float4 b0 = p[0], b1 = p[1];
            Bs[cb + 0][r] = b0.x; Bs[cb + 1][r] = b0.y; Bs[cb + 2][r] = b0.z; Bs[cb + 3][r] = b0.w;
            Bs[cb + 4][r] = b1.x; Bs[cb + 5][r] = b1.y; Bs[cb + 6][r] = b1.z; Bs[cb + 7][r] = b1.w;
        }
        __syncthreads();
#pragma unroll
        for (int kk = 0; kk < 16; kk++) {
            float a[8], bb[8];
#pragma unroll
            for (int i = 0; i < 8; i++) a[i]  = As[kk][ty * 8 + i];
#pragma unroll
            for (int j = 0; j < 8; j++) bb[j] = Bs[kk][tx * 8 + j];
#pragma unroll
            for (int i = 0; i < 8; i++)
#pragma unroll
                for (int j = 0; j < 8; j++) acc[i][j] += a[i] * bb[j];
        }
        __syncthreads();
    }

    float* O = g_o + (size_t)b * SS * CC;
#pragma unroll
    for (int i = 0; i < 8; i++)
#pragma unroll
        for (int j = 0; j < 8; j++)
            O[(size_t)(m0 + ty * 8 + i) * CC + n0 + tx * 8 + j] = acc[i][j];
}

// ---------------------------------------------------------------------------
// Output proj + residual: out[c][s] = x[c][s] + bo[c] + sum_c' wo[c][c'] o[s][c']
// ---------------------------------------------------------------------------
__global__ void __launch_bounds__(256) oproj_kernel(
    const float* __restrict__ wo, const float* __restrict__ bo,
    const float* __restrict__ x, float* __restrict__ out) {

    int b  = blockIdx.z;
    int m0 = blockIdx.y * 128;   // c_out
    int n0 = blockIdx.x * 128;   // s

    const float* O = g_o + (size_t)b * SS * CC;

    __shared__ float As[16][128];
    __shared__ float Bs[16][128];

    int tid = threadIdx.x;
    int tx = tid % 16, ty = tid / 16;

    float acc[8][8];
#pragma unroll
    for (int i = 0; i < 8; i++)
#pragma unroll
        for (int j = 0; j < 8; j++) acc[i][j] = 0.f;

    for (int k0 = 0; k0 < CC; k0 += 16) {
        int r = tid / 2, cb = (tid % 2) * 8;
        {   // A tile: wo[m0+r][k0+cb..] -> As[k][m]
            const float4* p = (const float4*)(wo + (size_t)(m0 + r) * CC + k0 + cb);
            float4 a0 = p[0], a1 = p[1];
            As[cb + 0][r] = a0.x; As[cb + 1][r] = a0.y; As[cb + 2][r] = a0.z; As[cb + 3][r] = a0.w;
            As[cb + 4][r] = a1.x; As[cb + 5][r] = a1.y; As[cb + 6][r] = a1.z; As[cb + 7][r] = a1.w;
        }
        {   // B tile: O[n0+r][k0+cb..] -> Bs[k][n]
            const float4* p = (const float4*)(O + (size_t)(n0 + r) * CC + k0 + cb);
            float4 b0 = p[0], b1 = p[1];
            Bs[cb + 0][r] = b0.x; Bs[cb + 1][r] = b0.y; Bs[cb + 2][r] = b0.z; Bs[cb + 3][r] = b0.w;
            Bs[cb + 4][r] = b1.x; Bs[cb + 5][r] = b1.y; Bs[cb + 6][r] = b1.z; Bs[cb + 7][r] = b1.w;
        }
        __syncthreads();
#pragma unroll
        for (int kk = 0; kk < 16; kk++) {
            float a[8], bb[8];
#pragma unroll
            for (int i = 0; i < 8; i++) a[i]  = As[kk][ty * 8 + i];
#pragma unroll
            for (int j = 0; j < 8; j++) bb[j] = Bs[kk][tx * 8 + j];
#pragma unroll
            for (int i = 0; i < 8; i++)
#pragma unroll
                for (int j = 0; j < 8; j++) acc[i][j] += a[i] * bb[j];
        }
        __syncthreads();
    }

#pragma unroll
    for (int i = 0; i < 8; i++) {
        int cc = m0 + ty * 8 + i;
        float bi = bo[cc];
        const float* xr = x   + (size_t)b * CC * SS + (size_t)cc * SS + n0 + tx * 8;
        float*       orow = out + (size_t)b * CC * SS + (size_t)cc * SS + n0 + tx * 8;
#pragma unroll
        for (int j = 0; j < 8; j++)
            orow[j] = xr[j] + bi + acc[i][j];
    }
}

// ---------------------------------------------------------------------------
extern "C" void kernel_launch(void* const* d_in, const int* in_sizes, int n_in,
                              void* d_out, int out_size) {
    const float* x     = (const float*)d_in[0];
    const float* gamma = (const float*)d_in[1];
    const float* wq    = (const float*)d_in[2];
    const float* bq    = (const float*)d_in[3];
    const float* wk    = (const float*)d_in[4];
    const float* bk    = (const float*)d_in[5];
    const float* wv    = (const float*)d_in[6];
    const float* bv    = (const float*)d_in[7];
    const float* wo    = (const float*)d_in[8];
    const float* bo    = (const float*)d_in[9];
    float* out = (float*)d_out;

    rms_kernel<<<dim3(SS / 256, BB), 256>>>(x, gamma);
    qkv_kernel<<<dim3(SS / 128, CC / 128, BB * 3), 256>>>(wq, bq, wk, bk, wv, bv);
    qk_kernel<<<dim3(SS / 128, SS / 128, BB), 256>>>();
    softmax_kernel<<<dim3(SS, BB), 256>>>();
    pv_kernel<<<dim3(CC / 128, SS / 128, BB), 256>>>();
    oproj_kernel<<<dim3(SS / 128, CC / 128, BB), 256>>>(wo, bo, x, out);
}

// round 2
// speedup vs baseline: 2.4560x; 2.4560x over previous
#include <cuda_runtime.h>
#include <math.h>
#include <stdint.h>

// Problem constants
#define BB   2
#define CC   512
#define SS   8192
#define NHW  1024

#define SQRT_C     22.627416997969522f
#define INV_SQRT_C 0.04419417382415922f

// Scratch
__device__ float g_hn[(size_t)BB * CC * SS];            // [b][c][s]
__device__ float g_q [(size_t)BB * CC * SS];            // [b][c][s]
__device__ float g_k [(size_t)BB * CC * SS];            // [b][c][s]
__device__ float g_v [(size_t)BB * CC * SS];            // [b][c][s]
__device__ float g_p [(size_t)BB * SS * SS];            // [b][sq][sk]
__device__ float g_o [(size_t)BB * SS * CC];            // [b][s][c]

// ---------------------------------------------------------------------------
// helpers
// ---------------------------------------------------------------------------
__device__ __forceinline__ uint32_t f2tf(float f) {
    uint32_t u;
    asm("cvt.rna.tf32.f32 %0, %1;" : "=r"(u) : "f"(f));
    return u;
}

__device__ __forceinline__ void mma_tf32(float* c, const uint32_t* a, const uint32_t* b) {
    asm volatile(
        "mma.sync.aligned.m16n8k8.row.col.f32.tf32.tf32.f32 "
        "{%0,%1,%2,%3}, {%4,%5,%6,%7}, {%8,%9}, {%0,%1,%2,%3};\n"
        : "+f"(c[0]), "+f"(c[1]), "+f"(c[2]), "+f"(c[3])
        : "r"(a[0]), "r"(a[1]), "r"(a[2]), "r"(a[3]), "r"(b[0]), "r"(b[1]));
}

#define LDPAD 136   // smem row stride (conflict-free fragment loads)

// Transpose-load: src row-major [.][ld]; tile rows row0..row0+127, cols col0..col0+15 -> dst[k][m]
__device__ __forceinline__ void load_T(uint32_t (*dst)[LDPAD], const float* __restrict__ src,
                                       size_t ld, int row0, int col0, int tid) {
    int r = tid >> 1, cb = (tid & 1) * 8;
    const float4* p = (const float4*)(src + (size_t)(row0 + r) * ld + col0 + cb);
    float4 a0 = p[0], a1 = p[1];
    dst[cb + 0][r] = f2tf(a0.x); dst[cb + 1][r] = f2tf(a0.y);
    dst[cb + 2][r] = f2tf(a0.z); dst[cb + 3][r] = f2tf(a0.w);
    dst[cb + 4][r] = f2tf(a1.x); dst[cb + 5][r] = f2tf(a1.y);
    dst[cb + 6][r] = f2tf(a1.z); dst[cb + 7][r] = f2tf(a1.w);
}

// Direct load: src [.][ld]; tile rows k0..k0+15, cols n0..n0+127 -> dst[k][n]
__device__ __forceinline__ void load_D(uint32_t (*dst)[LDPAD], const float* __restrict__ src,
                                       size_t ld, int k0, int n0, int tid) {
    int kr = tid >> 4, nc = (tid & 15) * 8;
    const float4* p = (const float4*)(src + (size_t)(k0 + kr) * ld + n0 + nc);
    float4 b0 = p[0], b1 = p[1];
    dst[kr][nc + 0] = f2tf(b0.x); dst[kr][nc + 1] = f2tf(b0.y);
    dst[kr][nc + 2] = f2tf(b0.z); dst[kr][nc + 3] = f2tf(b0.w);
    dst[kr][nc + 4] = f2tf(b1.x); dst[kr][nc + 5] = f2tf(b1.y);
    dst[kr][nc + 6] = f2tf(b1.z); dst[kr][nc + 7] = f2tf(b1.w);
}

// 16-deep K-slab of MMAs on the staged tiles
__device__ __forceinline__ void mma_slab(const uint32_t (*As)[LDPAD], const uint32_t (*Bs)[LDPAD],
                                         float acc[4][4][4], int wm, int wn, int qr, int qc) {
#pragma unroll
    for (int kb = 0; kb < 16; kb += 8) {
        uint32_t a[4][4], b[4][2];
#pragma unroll
        for (int mt = 0; mt < 4; mt++) {
            int m = wm + mt * 16;
            a[mt][0] = As[kb + qc][m + qr];
            a[mt][1] = As[kb + qc][m + qr + 8];
            a[mt][2] = As[kb + qc + 4][m + qr];
            a[mt][3] = As[kb + qc + 4][m + qr + 8];
        }
#pragma unroll
        for (int nt = 0; nt < 4; nt++) {
            int n = wn + nt * 8;
            b[nt][0] = Bs[kb + qc][n + qr];
            b[nt][1] = Bs[kb + qc + 4][n + qr];
        }
#pragma unroll
        for (int mt = 0; mt < 4; mt++)
#pragma unroll
            for (int nt = 0; nt < 4; nt++)
                mma_tf32(acc[mt][nt], a[mt], b[nt]);
    }
}

#define MMA_PRELUDE                                                     \
    __shared__ uint32_t As[16][LDPAD];                                  \
    __shared__ uint32_t Bs[16][LDPAD];                                  \
    int tid = threadIdx.x;                                              \
    int wid = tid >> 5, lane = tid & 31;                                \
    int wm = (wid >> 2) * 64, wn = (wid & 3) * 32;                      \
    int qr = lane >> 2, qc = lane & 3;                                  \
    float acc[4][4][4];                                                 \
    _Pragma("unroll") for (int mt = 0; mt < 4; mt++)                    \
    _Pragma("unroll") for (int nt = 0; nt < 4; nt++)                    \
    _Pragma("unroll") for (int i = 0; i < 4; i++) acc[mt][nt][i] = 0.f;

// ---------------------------------------------------------------------------
// RMS norm
// ---------------------------------------------------------------------------
__global__ void rms_kernel(const float* __restrict__ x,
                           const float* __restrict__ gamma) {
    int s = blockIdx.x * blockDim.x + threadIdx.x;
    int b = blockIdx.y;
    const float* xb = x + (size_t)b * CC * SS + s;
    float ss = 0.f;
#pragma unroll 8
    for (int c = 0; c < CC; c++) {
        float v = xb[(size_t)c * SS];
        ss += v * v;
    }
    float scale = SQRT_C / fmaxf(sqrtf(ss), 1e-12f);
    float* hb = g_hn + (size_t)b * CC * SS + s;
#pragma unroll 8
    for (int c = 0; c < CC; c++) {
        hb[(size_t)c * SS] = xb[(size_t)c * SS] * scale * gamma[c];
    }
}

// ---------------------------------------------------------------------------
// QKV projection: out[co][s] = sum_ci W[co][ci] * hn[ci][s] + bias
// ---------------------------------------------------------------------------
__global__ void __launch_bounds__(256) qkv_kernel(
    const float* __restrict__ wq, const float* __restrict__ bq,
    const float* __restrict__ wk, const float* __restrict__ bk,
    const float* __restrict__ wv, const float* __restrict__ bv) {

    int which = blockIdx.z % 3;
    int b     = blockIdx.z / 3;
    const float* W    = which == 0 ? wq : (which == 1 ? wk : wv);
    const float* bias = which == 0 ? bq : (which == 1 ? bk : bv);
    float* Cout = (which == 0 ? g_q : (which == 1 ? g_k : g_v)) + (size_t)b * CC * SS;
    const float* Bm = g_hn + (size_t)b * CC * SS;

    int m0 = blockIdx.y * 128, n0 = blockIdx.x * 128;
    MMA_PRELUDE

    for (int k0 = 0; k0 < CC; k0 += 16) {
        load_T(As, W, CC, m0, k0, tid);
        load_D(Bs, Bm, SS, k0, n0, tid);
        __syncthreads();
        mma_slab(As, Bs, acc, wm, wn, qr, qc);
        __syncthreads();
    }

#pragma unroll
    for (int mt = 0; mt < 4; mt++) {
        int m = m0 + wm + mt * 16 + qr;
        float bi0 = bias[m], bi1 = bias[m + 8];
#pragma unroll
        for (int nt = 0; nt < 4; nt++) {
            int n = n0 + wn + nt * 8 + qc * 2;
            float2 v0 = make_float2(acc[mt][nt][0] + bi0, acc[mt][nt][1] + bi0);
            float2 v1 = make_float2(acc[mt][nt][2] + bi1, acc[mt][nt][3] + bi1);
            *(float2*)&Cout[(size_t)m * SS + n]       = v0;
            *(float2*)&Cout[(size_t)(m + 8) * SS + n] = v1;
        }
    }
}

// ---------------------------------------------------------------------------
// QK^T (allowed tiles only)
// ---------------------------------------------------------------------------
__global__ void __launch_bounds__(256) qk_kernel() {
    int b  = blockIdx.z;
    int m0 = blockIdx.y * 128;   // sq
    int n0 = blockIdx.x * 128;   // sk
    if (n0 / NHW > m0 / NHW) return;

    const float* Q = g_q + (size_t)b * CC * SS;
    const float* K = g_k + (size_t)b * CC * SS;
    MMA_PRELUDE

    for (int k0 = 0; k0 < CC; k0 += 16) {
        load_D(As, Q, SS, k0, m0, tid);
        load_D(Bs, K, SS, k0, n0, tid);
        __syncthreads();
        mma_slab(As, Bs, acc, wm, wn, qr, qc);
        __syncthreads();
    }

    float* P = g_p + (size_t)b * SS * SS;
#pragma unroll
    for (int mt = 0; mt < 4; mt++) {
        int m = m0 + wm + mt * 16 + qr;
#pragma unroll
        for (int nt = 0; nt < 4; nt++) {
            int n = n0 + wn + nt * 8 + qc * 2;
            float2 v0 = make_float2(acc[mt][nt][0] * INV_SQRT_C, acc[mt][nt][1] * INV_SQRT_C);
            float2 v1 = make_float2(acc[mt][nt][2] * INV_SQRT_C, acc[mt][nt][3] * INV_SQRT_C);
            *(float2*)&P[(size_t)m * SS + n]       = v0;
            *(float2*)&P[(size_t)(m + 8) * SS + n] = v1;
        }
    }
}

// ---------------------------------------------------------------------------
// Row softmax, single pass, register-resident (L <= 8192 -> <= 32 / thread)
// ---------------------------------------------------------------------------
__global__ void __launch_bounds__(256) softmax_kernel() {
    int sq = blockIdx.x;
    int b  = blockIdx.y;
    float* row = g_p + ((size_t)b * SS + sq) * SS;
    int L = (sq / NHW + 1) * NHW;
    int n = L >> 8;                      // elems per thread (4..32)
    int tid = threadIdx.x;
    int lane = tid & 31, wid = tid >> 5;

    __shared__ float red[8];
    float vals[32];

    float m = -1e30f;
#pragma unroll
    for (int i = 0; i < 32; i++)
        if (i < n) { vals[i] = row[i * 256 + tid]; m = fmaxf(m, vals[i]); }
#pragma unroll
    for (int o = 16; o > 0; o >>= 1) m = fmaxf(m, __shfl_xor_sync(0xffffffffu, m, o));
    if (lane == 0) red[wid] = m;
    __syncthreads();
    float M = red[0];
#pragma unroll
    for (int i = 1; i < 8; i++) M = fmaxf(M, red[i]);
    __syncthreads();

    float s = 0.f;
#pragma unroll
    for (int i = 0; i < 32; i++)
        if (i < n) { vals[i] = __expf(vals[i] - M); s += vals[i]; }
#pragma unroll
    for (int o = 16; o > 0; o >>= 1) s += __shfl_xor_sync(0xffffffffu, s, o);
    if (lane == 0) red[wid] = s;
    __syncthreads();
    float S = 0.f;
#pragma unroll
    for (int i = 0; i < 8; i++) S += red[i];
    float inv = 1.f / S;
#pragma unroll
    for (int i = 0; i < 32; i++)
        if (i < n) row[i * 256 + tid] = vals[i] * inv;
}

// ---------------------------------------------------------------------------
// PV: o[sq][c] = sum_{sk<L} p[sq][sk] * v[c][sk]
// ---------------------------------------------------------------------------
__global__ void __launch_bounds__(256) pv_kernel() {
    int b  = blockIdx.z;
    int m0 = blockIdx.y * 128;   // sq
    int n0 = blockIdx.x * 128;   // c
    int L  = (m0 / NHW + 1) * NHW;

    const float* P = g_p + (size_t)b * SS * SS;
    const float* V = g_v + (size_t)b * CC * SS;
    MMA_PRELUDE

    for (int k0 = 0; k0 < L; k0 += 16) {
        load_T(As, P, SS, m0, k0, tid);
        load_T(Bs, V, SS, n0, k0, tid);
        __syncthreads();
        mma_slab(As, Bs, acc, wm, wn, qr, qc);
        __syncthreads();
    }

    float* O = g_o + (size_t)b * SS * CC;
#pragma unroll
    for (int mt = 0; mt < 4; mt++) {
        int m = m0 + wm + mt * 16 + qr;
#pragma unroll
        for (int nt = 0; nt < 4; nt++) {
            int n = n0 + wn + nt * 8 + qc * 2;
            float2 v0 = make_float2(acc[mt][nt][0], acc[mt][nt][1]);
            float2 v1 = make_float2(acc[mt][nt][2], acc[mt][nt][3]);
            *(float2*)&O[(size_t)m * CC + n]       = v0;
            *(float2*)&O[(size_t)(m + 8) * CC + n] = v1;
        }
    }
}

// ---------------------------------------------------------------------------
// Output proj + residual
// ---------------------------------------------------------------------------
__global__ void __launch_bounds__(256) oproj_kernel(
    const float* __restrict__ wo, const float* __restrict__ bo,
    const float* __restrict__ x, float* __restrict__ out) {

    int b  = blockIdx.z;
    int m0 = blockIdx.y * 128;   // c_out
    int n0 = blockIdx.x * 128;   // s

    const float* O = g_o + (size_t)b * SS * CC;
    MMA_PRELUDE

    for (int k0 = 0; k0 < CC; k0 += 16) {
        load_T(As, wo, CC, m0, k0, tid);
        load_T(Bs, O, CC, n0, k0, tid);
        __syncthreads();
        mma_slab(As, Bs, acc, wm, wn, qr, qc);
        __syncthreads();
    }

#pragma unroll
    for (int mt = 0; mt < 4; mt++) {
        int m = m0 + wm + mt * 16 + qr;
        float bi0 = bo[m], bi1 = bo[m + 8];
#pragma unroll
        for (int nt = 0; nt < 4; nt++) {
            int n = n0 + wn + nt * 8 + qc * 2;
            const float2 x0 = *(const float2*)&x[(size_t)b * CC * SS + (size_t)m * SS + n];
            const float2 x1 = *(const float2*)&x[(size_t)b * CC * SS + (size_t)(m + 8) * SS + n];
            float2 v0 = make_float2(acc[mt][nt][0] + bi0 + x0.x, acc[mt][nt][1] + bi0 + x0.y);
            float2 v1 = make_float2(acc[mt][nt][2] + bi1 + x1.x, acc[mt][nt][3] + bi1 + x1.y);
            *(float2*)&out[(size_t)b * CC * SS + (size_t)m * SS + n]       = v0;
            *(float2*)&out[(size_t)b * CC * SS + (size_t)(m + 8) * SS + n] = v1;
        }
    }
}

// ---------------------------------------------------------------------------
extern "C" void kernel_launch(void* const* d_in, const int* in_sizes, int n_in,
                              void* d_out, int out_size) {
    const float* x     = (const float*)d_in[0];
    const float* gamma = (const float*)d_in[1];
    const float* wq    = (const float*)d_in[2];
    const float* bq    = (const float*)d_in[3];
    const float* wk    = (const float*)d_in[4];
    const float* bk    = (const float*)d_in[5];
    const float* wv    = (const float*)d_in[6];
    const float* bv    = (const float*)d_in[7];
    const float* wo    = (const float*)d_in[8];
    const float* bo    = (const float*)d_in[9];
    float* out = (float*)d_out;

    rms_kernel<<<dim3(SS / 256, BB), 256>>>(x, gamma);
    qkv_kernel<<<dim3(SS / 128, CC / 128, BB * 3), 256>>>(wq, bq, wk, bk, wv, bv);
    qk_kernel<<<dim3(SS / 128, SS / 128, BB), 256>>>();
    softmax_kernel<<<dim3(SS, BB), 256>>>();
    pv_kernel<<<dim3(CC / 128, SS / 128, BB), 256>>>();
    oproj_kernel<<<dim3(SS / 128, CC / 128, BB), 256>>>(wo, bo, x, out);
}

// round 3
// speedup vs baseline: 5.4305x; 2.2111x over previous
#include <cuda_runtime.h>
#include <cuda_bf16.h>
#include <math.h>
#include <stdint.h>

#define BB 2
#define CC 512
#define SS 8192
#define NHW 1024
#define SQRT_C     22.627416997969522f
#define INV_SQRT_C 0.04419417382415922f

// bf16 intermediates
__device__ __nv_bfloat16 g_hn[(size_t)BB * CC * SS];   // [b][c][s]
__device__ __nv_bfloat16 g_q [(size_t)BB * CC * SS];   // [b][c][s]
__device__ __nv_bfloat16 g_k [(size_t)BB * CC * SS];   // [b][c][s]
__device__ __nv_bfloat16 g_v [(size_t)BB * CC * SS];   // [b][c][s]
__device__ __nv_bfloat16 g_p [(size_t)BB * SS * SS];   // [b][sq][sk]
__device__ __nv_bfloat16 g_o [(size_t)BB * SS * CC];   // [b][s][c]

// ---------------------------------------------------------------------------
// PTX helpers
// ---------------------------------------------------------------------------
__device__ __forceinline__ uint32_t smaddr(const void* p) {
    return (uint32_t)__cvta_generic_to_shared(p);
}
__device__ __forceinline__ void cp16(uint32_t dst, const void* src) {
    asm volatile("cp.async.cg.shared.global [%0], [%1], 16;\n" :: "r"(dst), "l"(src));
}
__device__ __forceinline__ void cp_commit() { asm volatile("cp.async.commit_group;\n"); }
template<int N> __device__ __forceinline__ void cp_wait() {
    asm volatile("cp.async.wait_group %0;\n" :: "n"(N));
}
__device__ __forceinline__ void ldsm4(uint32_t* r, uint32_t a) {
    asm volatile("ldmatrix.sync.aligned.m8n8.x4.shared.b16 {%0,%1,%2,%3}, [%4];"
                 : "=r"(r[0]), "=r"(r[1]), "=r"(r[2]), "=r"(r[3]) : "r"(a));
}
__device__ __forceinline__ void ldsm4t(uint32_t* r, uint32_t a) {
    asm volatile("ldmatrix.sync.aligned.m8n8.x4.trans.shared.b16 {%0,%1,%2,%3}, [%4];"
                 : "=r"(r[0]), "=r"(r[1]), "=r"(r[2]), "=r"(r[3]) : "r"(a));
}
__device__ __forceinline__ void mma16816(float* c, const uint32_t* a, const uint32_t* b) {
    asm volatile("mma.sync.aligned.m16n8k16.row.col.f32.bf16.bf16.f32 "
                 "{%0,%1,%2,%3},{%4,%5,%6,%7},{%8,%9},{%0,%1,%2,%3};"
                 : "+f"(c[0]), "+f"(c[1]), "+f"(c[2]), "+f"(c[3])
                 : "r"(a[0]), "r"(a[1]), "r"(a[2]), "r"(a[3]), "r"(b[0]), "r"(b[1]));
}

// smem layouts (bf16):
//   KM: [32 k][136]  (128 cols + 8 pad)  -- global rows are k, 128 contiguous m/n
//   MK: [128 r][40]  (32 k + 8 pad)      -- global rows are m/n, k contiguous
#define KMP 136
#define MKP 40

// cp.async stagers (2 x 16B chunks / thread, 512 chunks total per tile)
__device__ __forceinline__ void stageKM(__nv_bfloat16* buf, const __nv_bfloat16* g,
                                        size_t ld, int k0, int n0, int tid) {
    int c = tid * 2;
#pragma unroll
    for (int j = 0; j < 2; j++, c++) {
        int kr = c >> 4, off = (c & 15) << 3;
        cp16(smaddr(buf + kr * KMP + off), g + (size_t)(k0 + kr) * ld + n0 + off);
    }
}
__device__ __forceinline__ void stageMK(__nv_bfloat16* buf, const __nv_bfloat16* g,
                                        size_t ld, int r0, int k0, int tid) {
    int c = tid * 2;
#pragma unroll
    for (int j = 0; j < 2; j++, c++) {
        int row = c >> 2, off = (c & 3) << 3;
        cp16(smaddr(buf + row * MKP + off), g + (size_t)(r0 + row) * ld + k0 + off);
    }
}
// fp32 weight manual stage into MK layout
__device__ __forceinline__ void ldW4(float4 r[4], const float* W, int ldw,
                                     int m0, int k0, int tid) {
    int rr = tid >> 1, half = (tid & 1) * 16;
    const float* p = W + (size_t)(m0 + rr) * ldw + k0 + half;
    r[0] = *(const float4*)p;        r[1] = *(const float4*)(p + 4);
    r[2] = *(const float4*)(p + 8);  r[3] = *(const float4*)(p + 12);
}
__device__ __forceinline__ void stW4(__nv_bfloat16* buf, const float4 r[4], int tid) {
    int rr = tid >> 1, half = (tid & 1) * 16;
    __nv_bfloat16* d = buf + rr * MKP + half;
#pragma unroll
    for (int j = 0; j < 4; j++) {
        *(__nv_bfloat162*)(d + j * 4)     = __floats2bfloat162_rn(r[j].x, r[j].y);
        *(__nv_bfloat162*)(d + j * 4 + 2) = __floats2bfloat162_rn(r[j].z, r[j].w);
    }
}

// fragment loaders (K-slab 32 = two k16 steps)
__device__ __forceinline__ void fragA_KM(uint32_t a[2][4][4], uint32_t base, int wm, int lane) {
    int g = lane >> 3;
#pragma unroll
    for (int ks = 0; ks < 2; ks++)
#pragma unroll
        for (int mt = 0; mt < 4; mt++) {
            int row = ks * 16 + ((g >> 1) << 3) + (lane & 7);
            int col = wm + mt * 16 + ((g & 1) << 3);
            ldsm4t(a[ks][mt], base + (row * KMP + col) * 2);
        }
}
__device__ __forceinline__ void fragA_MK(uint32_t a[2][4][4], uint32_t base, int wm, int lane) {
    int g = lane >> 3;
#pragma unroll
    for (int ks = 0; ks < 2; ks++)
#pragma unroll
        for (int mt = 0; mt < 4; mt++) {
            int row = wm + mt * 16 + ((g & 1) << 3) + (lane & 7);
            int col = ks * 16 + ((g >> 1) << 3);
            ldsm4(a[ks][mt], base + (row * MKP + col) * 2);
        }
}
__device__ __forceinline__ void fragB_KM(uint32_t bfr[4][4], uint32_t base, int wn, int lane) {
    int g = lane >> 3;
#pragma unroll
    for (int nt = 0; nt < 4; nt++) {
        int row = (g << 3) + (lane & 7);
        int col = wn + nt * 8;
        ldsm4t(bfr[nt], base + (row * KMP + col) * 2);
    }
}
__device__ __forceinline__ void fragB_MK(uint32_t bfr[4][4], uint32_t base, int wn, int lane) {
    int g = lane >> 3;
#pragma unroll
    for (int nt = 0; nt < 4; nt++) {
        int row = wn + nt * 8 + (lane & 7);
        int col = g << 3;
        ldsm4(bfr[nt], base + (row * MKP + col) * 2);
    }
}
__device__ __forceinline__ void mma_all(float acc[4][4][4], uint32_t a[2][4][4],
                                        uint32_t bfr[4][4]) {
#pragma unroll
    for (int ks = 0; ks < 2; ks++)
#pragma unroll
        for (int mt = 0; mt < 4; mt++)
#pragma unroll
            for (int nt = 0; nt < 4; nt++)
                mma16816(acc[mt][nt], a[ks][mt], &bfr[nt][ks * 2]);
}

#define MMA_VARS                                                      \
    int tid = threadIdx.x, lane = tid & 31, wid = tid >> 5;           \
    int wm = (wid >> 2) * 64, wn = (wid & 3) * 32;                    \
    int qr = lane >> 2, qc = lane & 3;                                \
    float acc[4][4][4];                                               \
    _Pragma("unroll") for (int mt = 0; mt < 4; mt++)                  \
    _Pragma("unroll") for (int nt = 0; nt < 4; nt++)                  \
    _Pragma("unroll") for (int i = 0; i < 4; i++) acc[mt][nt][i] = 0.f;

// ---------------------------------------------------------------------------
// RMS norm (bf16 out)
// ---------------------------------------------------------------------------
__global__ void rms_kernel(const float* __restrict__ x,
                           const float* __restrict__ gamma) {
    int s = blockIdx.x * blockDim.x + threadIdx.x;
    int b = blockIdx.y;
    const float* xb = x + (size_t)b * CC * SS + s;
    float ss = 0.f;
#pragma unroll 8
    for (int c = 0; c < CC; c++) {
        float v = xb[(size_t)c * SS];
        ss += v * v;
    }
    float scale = SQRT_C / fmaxf(sqrtf(ss), 1e-12f);
    __nv_bfloat16* hb = g_hn + (size_t)b * CC * SS + s;
#pragma unroll 8
    for (int c = 0; c < CC; c++)
        hb[(size_t)c * SS] = __float2bfloat16_rn(xb[(size_t)c * SS] * scale * gamma[c]);
}

// ---------------------------------------------------------------------------
// QKV projection: A = W (fp32, MK manual), B = hn (KM async)
// ---------------------------------------------------------------------------
__global__ void __launch_bounds__(256) qkv_kernel(
    const float* __restrict__ wq, const float* __restrict__ bq,
    const float* __restrict__ wk, const float* __restrict__ bk,
    const float* __restrict__ wv, const float* __restrict__ bv) {

    int which = blockIdx.z % 3;
    int b     = blockIdx.z / 3;
    const float* W    = which == 0 ? wq : (which == 1 ? wk : wv);
    const float* bias = which == 0 ? bq : (which == 1 ? bk : bv);
    __nv_bfloat16* Cout = (which == 0 ? g_q : (which == 1 ? g_k : g_v)) + (size_t)b * CC * SS;
    const __nv_bfloat16* HN = g_hn + (size_t)b * CC * SS;

    int m0 = blockIdx.y * 128, n0 = blockIdx.x * 128;

    __shared__ __align__(16) __nv_bfloat16 sA[2][128 * MKP];
    __shared__ __align__(16) __nv_bfloat16 sB[2][32 * KMP];
    MMA_VARS

    float4 wreg[4];
    ldW4(wreg, W, CC, m0, 0, tid);
    stW4(sA[0], wreg, tid);
    stageKM(sB[0], HN, SS, 0, n0, tid);
    cp_commit();

    for (int it = 0; it < 16; it++) {
        int k0 = it * 32;
        bool more = it < 15;
        if (more) {
            ldW4(wreg, W, CC, m0, k0 + 32, tid);
            stageKM(sB[(it + 1) & 1], HN, SS, k0 + 32, n0, tid);
            cp_commit();
            cp_wait<1>();
        } else cp_wait<0>();
        __syncthreads();
        if (more) stW4(sA[(it + 1) & 1], wreg, tid);

        uint32_t a[2][4][4], bfr[4][4];
        fragA_MK(a, smaddr(sA[it & 1]), wm, lane);
        fragB_KM(bfr, smaddr(sB[it & 1]), wn, lane);
        mma_all(acc, a, bfr);
        __syncthreads();
    }

#pragma unroll
    for (int mt = 0; mt < 4; mt++) {
        int m = m0 + wm + mt * 16 + qr;
        float bi0 = bias[m], bi1 = bias[m + 8];
#pragma unroll
        for (int nt = 0; nt < 4; nt++) {
            int n = n0 + wn + nt * 8 + qc * 2;
            *(__nv_bfloat162*)&Cout[(size_t)m * SS + n] =
                __floats2bfloat162_rn(acc[mt][nt][0] + bi0, acc[mt][nt][1] + bi0);
            *(__nv_bfloat162*)&Cout[(size_t)(m + 8) * SS + n] =
                __floats2bfloat162_rn(acc[mt][nt][2] + bi1, acc[mt][nt][3] + bi1);
        }
    }
}

// ---------------------------------------------------------------------------
// QK^T: A = Q (KM), B = K (KM); write bf16 scores (scaled)
// ---------------------------------------------------------------------------
__global__ void __launch_bounds__(256) qk_kernel() {
    int b  = blockIdx.z;
    int m0 = blockIdx.y * 128;   // sq
    int n0 = blockIdx.x * 128;   // sk
    if (n0 / NHW > m0 / NHW) return;

    const __nv_bfloat16* Q = g_q + (size_t)b * CC * SS;
    const __nv_bfloat16* K = g_k + (size_t)b * CC * SS;

    __shared__ __align__(16) __nv_bfloat16 sA[2][32 * KMP];
    __shared__ __align__(16) __nv_bfloat16 sB[2][32 * KMP];
    MMA_VARS

    stageKM(sA[0], Q, SS, 0, m0, tid);
    stageKM(sB[0], K, SS, 0, n0, tid);
    cp_commit();

    for (int it = 0; it < 16; it++) {
        int k0 = it * 32;
        if (it < 15) {
            stageKM(sA[(it + 1) & 1], Q, SS, k0 + 32, m0, tid);
            stageKM(sB[(it + 1) & 1], K, SS, k0 + 32, n0, tid);
            cp_commit();
            cp_wait<1>();
        } else cp_wait<0>();
        __syncthreads();

        uint32_t a[2][4][4], bfr[4][4];
        fragA_KM(a, smaddr(sA[it & 1]), wm, lane);
        fragB_KM(bfr, smaddr(sB[it & 1]), wn, lane);
        mma_all(acc, a, bfr);
        __syncthreads();
    }

    __nv_bfloat16* P = g_p + (size_t)b * SS * SS;
#pragma unroll
    for (int mt = 0; mt < 4; mt++) {
        int m = m0 + wm + mt * 16 + qr;
#pragma unroll
        for (int nt = 0; nt < 4; nt++) {
            int n = n0 + wn + nt * 8 + qc * 2;
            *(__nv_bfloat162*)&P[(size_t)m * SS + n] =
                __floats2bfloat162_rn(acc[mt][nt][0] * INV_SQRT_C, acc[mt][nt][1] * INV_SQRT_C);
            *(__nv_bfloat162*)&P[(size_t)(m + 8) * SS + n] =
                __floats2bfloat162_rn(acc[mt][nt][2] * INV_SQRT_C, acc[mt][nt][3] * INV_SQRT_C);
        }
    }
}

// ---------------------------------------------------------------------------
// Row softmax in-place on bf16 scores (register-resident)
// ---------------------------------------------------------------------------
__global__ void __launch_bounds__(256) softmax_kernel() {
    int sq = blockIdx.x;
    int b  = blockIdx.y;
    __nv_bfloat162* row2 = (__nv_bfloat162*)(g_p + ((size_t)b * SS + sq) * SS);
    int L = (sq / NHW + 1) * NHW;
    int n2 = L >> 9;                       // bf162 units per thread (2..16)
    int tid = threadIdx.x;
    int lane = tid & 31, wid = tid >> 5;

    __shared__ float red[8];
    float2 vals[16];

    float m = -1e30f;
#pragma unroll
    for (int i = 0; i < 16; i++)
        if (i < n2) {
            vals[i] = __bfloat1622float2(row2[i * 256 + tid]);
            m = fmaxf(m, fmaxf(vals[i].x, vals[i].y));
        }
#pragma unroll
    for (int o = 16; o > 0; o >>= 1) m = fmaxf(m, __shfl_xor_sync(0xffffffffu, m, o));
    if (lane == 0) red[wid] = m;
    __syncthreads();
    float M = red[0];
#pragma unroll
    for (int i = 1; i < 8; i++) M = fmaxf(M, red[i]);
    __syncthreads();

    float s = 0.f;
#pragma unroll
    for (int i = 0; i < 16; i++)
        if (i < n2) {
            vals[i].x = __expf(vals[i].x - M);
            vals[i].y = __expf(vals[i].y - M);
            s += vals[i].x + vals[i].y;
        }
#pragma unroll
    for (int o = 16; o > 0; o >>= 1) s += __shfl_xor_sync(0xffffffffu, s, o);
    if (lane == 0) red[wid] = s;
    __syncthreads();
    float S = 0.f;
#pragma unroll
    for (int i = 0; i < 8; i++) S += red[i];
    float inv = 1.f / S;
#pragma unroll
    for (int i = 0; i < 16; i++)
        if (i < n2)
            row2[i * 256 + tid] = __floats2bfloat162_rn(vals[i].x * inv, vals[i].y * inv);
}

// ---------------------------------------------------------------------------
// PV: A = P (MK), B = V (MK as [n=c][k=s]); o[sq][c] bf16
// ---------------------------------------------------------------------------
__global__ void __launch_bounds__(256) pv_kernel() {
    int b  = blockIdx.z;
    int m0 = blockIdx.y * 128;   // sq
    int n0 = blockIdx.x * 128;   // c
    int L  = (m0 / NHW + 1) * NHW;
    int nIt = L / 32;

    const __nv_bfloat16* P = g_p + (size_t)b * SS * SS;
    const __nv_bfloat16* V = g_v + (size_t)b * CC * SS;

    __shared__ __align__(16) __nv_bfloat16 sA[2][128 * MKP];
    __shared__ __align__(16) __nv_bfloat16 sB[2][128 * MKP];
    MMA_VARS

    stageMK(sA[0], P, SS, m0, 0, tid);
    stageMK(sB[0], V, SS, n0, 0, tid);
    cp_commit();

    for (int it = 0; it < nIt; it++) {
        int k0 = it * 32;
        if (it + 1 < nIt) {
            stageMK(sA[(it + 1) & 1], P, SS, m0, k0 + 32, tid);
            stageMK(sB[(it + 1) & 1], V, SS, n0, k0 + 32, tid);
            cp_commit();
            cp_wait<1>();
        } else cp_wait<0>();
        __syncthreads();

        uint32_t a[2][4][4], bfr[4][4];
        fragA_MK(a, smaddr(sA[it & 1]), wm, lane);
        fragB_MK(bfr, smaddr(sB[it & 1]), wn, lane);
        mma_all(acc, a, bfr);
        __syncthreads();
    }

    __nv_bfloat16* O = g_o + (size_t)b * SS * CC;
#pragma unroll
    for (int mt = 0; mt < 4; mt++) {
        int m = m0 + wm + mt * 16 + qr;
#pragma unroll
        for (int nt = 0; nt < 4; nt++) {
            int n = n0 + wn + nt * 8 + qc * 2;
            *(__nv_bfloat162*)&O[(size_t)m * CC + n] =
                __floats2bfloat162_rn(acc[mt][nt][0], acc[mt][nt][1]);
            *(__nv_bfloat162*)&O[(size_t)(m + 8) * CC + n] =
                __floats2bfloat162_rn(acc[mt][nt][2], acc[mt][nt][3]);
        }
    }
}

// ---------------------------------------------------------------------------
// Output proj + residual: A = wo (fp32 MK manual), B = g_o (MK, [n=s][k=c])
// ---------------------------------------------------------------------------
__global__ void __launch_bounds__(256) oproj_kernel(
    const float* __restrict__ wo, const float* __restrict__ bo,
    const float* __restrict__ x, float* __restrict__ out) {

    int b  = blockIdx.z;
    int m0 = blockIdx.y * 128;   // c_out
    int n0 = blockIdx.x * 128;   // s

    const __nv_bfloat16* O = g_o + (size_t)b * SS * CC;

    __shared__ __align__(16) __nv_bfloat16 sA[2][128 * MKP];
    __shared__ __align__(16) __nv_bfloat16 sB[2][128 * MKP];
    MMA_VARS

    float4 wreg[4];
    ldW4(wreg, wo, CC, m0, 0, tid);
    stW4(sA[0], wreg, tid);
    stageMK(sB[0], O, CC, n0, 0, tid);
    cp_commit();

    for (int it = 0; it < 16; it++) {
        int k0 = it * 32;
        bool more = it < 15;
        if (more) {
            ldW4(wreg, wo, CC, m0, k0 + 32, tid);
            stageMK(sB[(it + 1) & 1], O, CC, n0, k0 + 32, tid);
            cp_commit();
            cp_wait<1>();
        } else cp_wait<0>();
        __syncthreads();
        if (more) stW4(sA[(it + 1) & 1], wreg, tid);

        uint32_t a[2][4][4], bfr[4][4];
        fragA_MK(a, smaddr(sA[it & 1]), wm, lane);
        fragB_MK(bfr, smaddr(sB[it & 1]), wn, lane);
        mma_all(acc, a, bfr);
        __syncthreads();
    }

#pragma unroll
    for (int mt = 0; mt < 4; mt++) {
        int m = m0 + wm + mt * 16 + qr;
        float bi0 = bo[m], bi1 = bo[m + 8];
#pragma unroll
        for (int nt = 0; nt < 4; nt++) {
            int n = n0 + wn + nt * 8 + qc * 2;
            const float2 x0 = *(const float2*)&x[(size_t)b * CC * SS + (size_t)m * SS + n];
            const float2 x1 = *(const float2*)&x[(size_t)b * CC * SS + (size_t)(m + 8) * SS + n];
            float2 v0 = make_float2(acc[mt][nt][0] + bi0 + x0.x, acc[mt][nt][1] + bi0 + x0.y);
            float2 v1 = make_float2(acc[mt][nt][2] + bi1 + x1.x, acc[mt][nt][3] + bi1 + x1.y);
            *(float2*)&out[(size_t)b * CC * SS + (size_t)m * SS + n]       = v0;
            *(float2*)&out[(size_t)b * CC * SS + (size_t)(m + 8) * SS + n] = v1;
        }
    }
}

// ---------------------------------------------------------------------------
extern "C" void kernel_launch(void* const* d_in, const int* in_sizes, int n_in,
                              void* d_out, int out_size) {
    const float* x     = (const float*)d_in[0];
    const float* gamma = (const float*)d_in[1];
    const float* wq    = (const float*)d_in[2];
    const float* bq    = (const float*)d_in[3];
    const float* wk    = (const float*)d_in[4];
    const float* bk    = (const float*)d_in[5];
    const float* wv    = (const float*)d_in[6];
    const float* bv    = (const float*)d_in[7];
    const float* wo    = (const float*)d_in[8];
    const float* bo    = (const float*)d_in[9];
    float* out = (float*)d_out;

    rms_kernel<<<dim3(SS / 256, BB), 256>>>(x, gamma);
    qkv_kernel<<<dim3(SS / 128, CC / 128, BB * 3), 256>>>(wq, bq, wk, bk, wv, bv);
    qk_kernel<<<dim3(SS / 128, SS / 128, BB), 256>>>();
    softmax_kernel<<<dim3(SS, BB), 256>>>();
    pv_kernel<<<dim3(CC / 128, SS / 128, BB), 256>>>();
    oproj_kernel<<<dim3(SS / 128, CC / 128, BB), 256>>>(wo, bo, x, out);
}

// round 5
// speedup vs baseline: 7.7880x; 1.4341x over previous
#include <cuda_runtime.h>
#include <cuda_bf16.h>
#include <math.h>
#include <stdint.h>

#define BB 2
#define CC 512
#define SS 8192
#define NHW 1024
#define SQRT_C     22.627416997969522f
#define INV_SQRT_C 0.04419417382415922f

#define STAGES 4
#define KSLAB  32
#define KMP 136            // KM tile row stride (bf16): 32 k-rows x 128 cols (+8 pad)
#define MKP 40             // MK tile row stride (bf16): 128 rows x 32 k (+8 pad)
#define SZ_KM (32 * KMP * 2)    // 8704 B
#define SZ_MK (128 * MKP * 2)   // 10240 B
#define DYN_SMEM (2 * STAGES * SZ_MK)   // 81920 B (max of all kernels)

// Scratch (bf16 intermediates)
__device__ __nv_bfloat16 g_hn[(size_t)BB * CC * SS];   // [b][c][s]
__device__ __nv_bfloat16 g_q [(size_t)BB * CC * SS];   // [b][c][s]
__device__ __nv_bfloat16 g_k [(size_t)BB * CC * SS];   // [b][c][s]
__device__ __nv_bfloat16 g_v [(size_t)BB * CC * SS];   // [b][c][s]
__device__ __nv_bfloat16 g_p [(size_t)BB * SS * SS];   // [b][sq][sk]
__device__ __nv_bfloat16 g_o [(size_t)BB * SS * CC];   // [b][s][c]
__device__ __nv_bfloat16 g_w [4][(size_t)CC * CC];     // bf16 weights [co][ci]

// ---------------------------------------------------------------------------
// PTX helpers
// ---------------------------------------------------------------------------
__device__ __forceinline__ uint32_t smaddr(const void* p) {
    return (uint32_t)__cvta_generic_to_shared(p);
}
__device__ __forceinline__ void cp16(uint32_t d, const void* s) {
    asm volatile("cp.async.cg.shared.global [%0], [%1], 16;\n" :: "r"(d), "l"(s));
}
__device__ __forceinline__ void cp_commit() { asm volatile("cp.async.commit_group;\n"); }
template<int N> __device__ __forceinline__ void cp_wait() {
    asm volatile("cp.async.wait_group %0;\n" :: "n"(N));
}
__device__ __forceinline__ void ldsm4(uint32_t* r, uint32_t a) {
    asm volatile("ldmatrix.sync.aligned.m8n8.x4.shared.b16 {%0,%1,%2,%3}, [%4];"
                 : "=r"(r[0]), "=r"(r[1]), "=r"(r[2]), "=r"(r[3]) : "r"(a));
}
__device__ __forceinline__ void ldsm4t(uint32_t* r, uint32_t a) {
    asm volatile("ldmatrix.sync.aligned.m8n8.x4.trans.shared.b16 {%0,%1,%2,%3}, [%4];"
                 : "=r"(r[0]), "=r"(r[1]), "=r"(r[2]), "=r"(r[3]) : "r"(a));
}
__device__ __forceinline__ void mma16816(float* c, const uint32_t* a, const uint32_t* b) {
    asm volatile("mma.sync.aligned.m16n8k16.row.col.f32.bf16.bf16.f32 "
                 "{%0,%1,%2,%3},{%4,%5,%6,%7},{%8,%9},{%0,%1,%2,%3};"
                 : "+f"(c[0]), "+f"(c[1]), "+f"(c[2]), "+f"(c[3])
                 : "r"(a[0]), "r"(a[1]), "r"(a[2]), "r"(a[3]), "r"(b[0]), "r"(b[1]));
}

// ---------------------------------------------------------------------------
// stagers: 128 threads, 4 x 16B chunks each
// ---------------------------------------------------------------------------
__device__ __forceinline__ void stageKM(uint32_t dst, const __nv_bfloat16* g,
                                        int ld, int k0, int n0, int tid) {
#pragma unroll
    for (int j = 0; j < 4; j++) {
        int c = j * 128 + tid;
        int kr = c >> 4, off = (c & 15) << 3;
        cp16(dst + (uint32_t)(kr * KMP + off) * 2, g + (size_t)(k0 + kr) * ld + n0 + off);
    }
}
__device__ __forceinline__ void stageMK(uint32_t dst, const __nv_bfloat16* g,
                                        int ld, int r0, int k0, int tid) {
#pragma unroll
    for (int j = 0; j < 4; j++) {
        int c = j * 128 + tid;
        int row = c >> 2, off = (c & 3) << 3;
        cp16(dst + (uint32_t)(row * MKP + off) * 2, g + (size_t)(r0 + row) * ld + k0 + off);
    }
}

// ---------------------------------------------------------------------------
// fragment loaders (warp tile 64x64, K-slab 32)
// ---------------------------------------------------------------------------
__device__ __forceinline__ void fragA_KM(uint32_t a[4][4], uint32_t base,
                                         int wm, int lane, int ks) {
    int g = lane >> 3;
#pragma unroll
    for (int mt = 0; mt < 4; mt++) {
        int row = ks * 16 + ((g >> 1) << 3) + (lane & 7);
        int col = wm + mt * 16 + ((g & 1) << 3);
        ldsm4t(a[mt], base + (uint32_t)(row * KMP + col) * 2);
    }
}
__device__ __forceinline__ void fragA_MK(uint32_t a[4][4], uint32_t base,
                                         int wm, int lane, int ks) {
    int g = lane >> 3;
#pragma unroll
    for (int mt = 0; mt < 4; mt++) {
        int row = wm + mt * 16 + ((g & 1) << 3) + (lane & 7);
        int col = ks * 16 + ((g >> 1) << 3);
        ldsm4(a[mt], base + (uint32_t)(row * MKP + col) * 2);
    }
}
__device__ __forceinline__ void fragB_KM(uint32_t b[8][4], uint32_t base, int wn, int lane) {
    int g = lane >> 3;
#pragma unroll
    for (int nt = 0; nt < 8; nt++) {
        int row = (g << 3) + (lane & 7);
        int col = wn + nt * 8;
        ldsm4t(b[nt], base + (uint32_t)(row * KMP + col) * 2);
    }
}
__device__ __forceinline__ void fragB_MK(uint32_t b[8][4], uint32_t base, int wn, int lane) {
    int g = lane >> 3;
#pragma unroll
    for (int nt = 0; nt < 8; nt++) {
        int row = wn + nt * 8 + (lane & 7);
        int col = g << 3;
        ldsm4(b[nt], base + (uint32_t)(row * MKP + col) * 2);
    }
}

#define GEMM_VARS                                                     \
    extern __shared__ __align__(16) char dynsm[];                     \
    uint32_t sbase = smaddr(dynsm);                                   \
    int tid = threadIdx.x, lane = tid & 31, wid = tid >> 5;           \
    int wm = (wid >> 1) * 64, wn = (wid & 1) * 64;                    \
    int qr = lane >> 2, qc = lane & 3;                                \
    float acc[4][8][4];                                               \
    _Pragma("unroll") for (int mt = 0; mt < 4; mt++)                  \
    _Pragma("unroll") for (int nt = 0; nt < 8; nt++)                  \
    _Pragma("unroll") for (int i = 0; i < 4; i++) acc[mt][nt][i] = 0.f;

// compute one K-slab from staged buffers; FA in {fragA_KM, fragA_MK}, FB likewise
#define SLAB_COMPUTE(FA, FB, baseA, baseB)                            \
    {                                                                 \
        uint32_t bfr[8][4];                                           \
        FB(bfr, (baseB), wn, lane);                                   \
        _Pragma("unroll")                                             \
        for (int ks = 0; ks < 2; ks++) {                              \
            uint32_t afr[4][4];                                       \
            FA(afr, (baseA), wm, lane, ks);                           \
            _Pragma("unroll") for (int mt = 0; mt < 4; mt++)          \
            _Pragma("unroll") for (int nt = 0; nt < 8; nt++)          \
                mma16816(acc[mt][nt], afr[mt], &bfr[nt][ks * 2]);     \
        }                                                             \
    }

// ---------------------------------------------------------------------------
// prep: fp32 weights -> bf16
// ---------------------------------------------------------------------------
__global__ void prep_w_kernel(const float* __restrict__ wq, const float* __restrict__ wk,
                              const float* __restrict__ wv, const float* __restrict__ wo) {
    int which = blockIdx.y;
    const float* w = which == 0 ? wq : which == 1 ? wk : which == 2 ? wv : wo;
    int i = blockIdx.x * 256 + threadIdx.x;
    g_w[which][i] = __float2bfloat16_rn(w[i]);
}

// ---------------------------------------------------------------------------
// RMS norm (bf16 out, [c][s])
// ---------------------------------------------------------------------------
__global__ void rms_kernel(const float* __restrict__ x,
                           const float* __restrict__ gamma) {
    int s = blockIdx.x * blockDim.x + threadIdx.x;
    int b = blockIdx.y;
    const float* xb = x + (size_t)b * CC * SS + s;
    float ss = 0.f;
#pragma unroll 8
    for (int c = 0; c < CC; c++) {
        float v = xb[(size_t)c * SS];
        ss += v * v;
    }
    float scale = SQRT_C / fmaxf(sqrtf(ss), 1e-12f);
    __nv_bfloat16* hb = g_hn + (size_t)b * CC * SS + s;
#pragma unroll 8
    for (int c = 0; c < CC; c++)
        hb[(size_t)c * SS] = __float2bfloat16_rn(xb[(size_t)c * SS] * scale * gamma[c]);
}

// ---------------------------------------------------------------------------
// QKV projection: D[co][s] = W[co][:] . hn[:][s]   A = W (MK), B = hn (KM)
// ---------------------------------------------------------------------------
__global__ void __launch_bounds__(128) qkv_kernel(
    const float* __restrict__ bq, const float* __restrict__ bk,
    const float* __restrict__ bv) {

    int which = blockIdx.z % 3;
    int b     = blockIdx.z / 3;
    const __nv_bfloat16* W = g_w[which];
    const float* bias = which == 0 ? bq : (which == 1 ? bk : bv);
    __nv_bfloat16* Cout = (which == 0 ? g_q : (which == 1 ? g_k : g_v)) + (size_t)b * CC * SS;
    const __nv_bfloat16* HN = g_hn + (size_t)b * CC * SS;

    int m0 = blockIdx.y * 128, n0 = blockIdx.x * 128;
    GEMM_VARS
    uint32_t tbA = sbase, tbB = sbase + STAGES * SZ_MK;

    for (int s = 0; s < STAGES - 1; s++) {
        stageMK(tbA + s * SZ_MK, W, CC, m0, s * KSLAB, tid);
        stageKM(tbB + s * SZ_KM, HN, SS, s * KSLAB, n0, tid);
        cp_commit();
    }
    const int nIt = CC / KSLAB;   // 16
    for (int i = 0; i < nIt; i++) {
        cp_wait<STAGES - 2>();
        __syncthreads();
        int sl = i % STAGES;
        SLAB_COMPUTE(fragA_MK, fragB_KM, tbA + sl * SZ_MK, tbB + sl * SZ_KM);
        int pf = i + STAGES - 1;
        if (pf < nIt) {
            int ps = pf % STAGES;
            stageMK(tbA + ps * SZ_MK, W, CC, m0, pf * KSLAB, tid);
            stageKM(tbB + ps * SZ_KM, HN, SS, pf * KSLAB, n0, tid);
            cp_commit();
        }
    }

#pragma unroll
    for (int mt = 0; mt < 4; mt++) {
        int m = m0 + wm + mt * 16 + qr;
        float bi0 = bias[m], bi1 = bias[m + 8];
#pragma unroll
        for (int nt = 0; nt < 8; nt++) {
            int n = n0 + wn + nt * 8 + qc * 2;
            *(__nv_bfloat162*)&Cout[(size_t)m * SS + n] =
                __floats2bfloat162_rn(acc[mt][nt][0] + bi0, acc[mt][nt][1] + bi0);
            *(__nv_bfloat162*)&Cout[(size_t)(m + 8) * SS + n] =
                __floats2bfloat162_rn(acc[mt][nt][2] + bi1, acc[mt][nt][3] + bi1);
        }
    }
}

// ---------------------------------------------------------------------------
// QK^T (allowed tiles only): A = Q (KM), B = K (KM)
// ---------------------------------------------------------------------------
__global__ void __launch_bounds__(128) qk_kernel() {
    int b  = blockIdx.z;
    int m0 = blockIdx.y * 128;   // sq
    int n0 = blockIdx.x * 128;   // sk
    if (n0 / NHW > m0 / NHW) return;

    const __nv_bfloat16* Q = g_q + (size_t)b * CC * SS;
    const __nv_bfloat16* K = g_k + (size_t)b * CC * SS;
    GEMM_VARS
    uint32_t tbA = sbase, tbB = sbase + STAGES * SZ_KM;

    for (int s = 0; s < STAGES - 1; s++) {
        stageKM(tbA + s * SZ_KM, Q, SS, s * KSLAB, m0, tid);
        stageKM(tbB + s * SZ_KM, K, SS, s * KSLAB, n0, tid);
        cp_commit();
    }
    const int nIt = CC / KSLAB;
    for (int i = 0; i < nIt; i++) {
        cp_wait<STAGES - 2>();
        __syncthreads();
        int sl = i % STAGES;
        SLAB_COMPUTE(fragA_KM, fragB_KM, tbA + sl * SZ_KM, tbB + sl * SZ_KM);
        int pf = i + STAGES - 1;
        if (pf < nIt) {
            int ps = pf % STAGES;
            stageKM(tbA + ps * SZ_KM, Q, SS, pf * KSLAB, m0, tid);
            stageKM(tbB + ps * SZ_KM, K, SS, pf * KSLAB, n0, tid);
            cp_commit();
        }
    }

    __nv_bfloat16* P = g_p + (size_t)b * SS * SS;
#pragma unroll
    for (int mt = 0; mt < 4; mt++) {
        int m = m0 + wm + mt * 16 + qr;
#pragma unroll
        for (int nt = 0; nt < 8; nt++) {
            int n = n0 + wn + nt * 8 + qc * 2;
            *(__nv_bfloat162*)&P[(size_t)m * SS + n] =
                __floats2bfloat162_rn(acc[mt][nt][0] * INV_SQRT_C, acc[mt][nt][1] * INV_SQRT_C);
            *(__nv_bfloat162*)&P[(size_t)(m + 8) * SS + n] =
                __floats2bfloat162_rn(acc[mt][nt][2] * INV_SQRT_C, acc[mt][nt][3] * INV_SQRT_C);
        }
    }
}

// ---------------------------------------------------------------------------
// Row softmax in-place on bf16 scores (register-resident)
// ---------------------------------------------------------------------------
__global__ void __launch_bounds__(256) softmax_kernel() {
    int sq = blockIdx.x;
    int b  = blockIdx.y;
    __nv_bfloat162* row2 = (__nv_bfloat162*)(g_p + ((size_t)b * SS + sq) * SS);
    int L = (sq / NHW + 1) * NHW;
    int n2 = L >> 9;
    int tid = threadIdx.x;
    int lane = tid & 31, wid = tid >> 5;

    __shared__ float red[8];
    float2 vals[16];

    float m = -1e30f;
#pragma unroll
    for (int i = 0; i < 16; i++)
        if (i < n2) {
            vals[i] = __bfloat1622float2(row2[i * 256 + tid]);
            m = fmaxf(m, fmaxf(vals[i].x, vals[i].y));
        }
#pragma unroll
    for (int o = 16; o > 0; o >>= 1) m = fmaxf(m, __shfl_xor_sync(0xffffffffu, m, o));
    if (lane == 0) red[wid] = m;
    __syncthreads();
    float M = red[0];
#pragma unroll
    for (int i = 1; i < 8; i++) M = fmaxf(M, red[i]);
    __syncthreads();

    float s = 0.f;
#pragma unroll
    for (int i = 0; i < 16; i++)
        if (i < n2) {
            vals[i].x = __expf(vals[i].x - M);
            vals[i].y = __expf(vals[i].y - M);
            s += vals[i].x + vals[i].y;
        }
#pragma unroll
    for (int o = 16; o > 0; o >>= 1) s += __shfl_xor_sync(0xffffffffu, s, o);
    if (lane == 0) red[wid] = s;
    __syncthreads();
    float S = 0.f;
#pragma unroll
    for (int i = 0; i < 8; i++) S += red[i];
    float inv = 1.f / S;
#pragma unroll
    for (int i = 0; i < 16; i++)
        if (i < n2)
            row2[i * 256 + tid] = __floats2bfloat162_rn(vals[i].x * inv, vals[i].y * inv);
}

// ---------------------------------------------------------------------------
// PV: D[sq][c] = P[sq][:L] . v[c][:L]   A = P (MK), B = V (MK rows c)
// ---------------------------------------------------------------------------
__global__ void __launch_bounds__(128) pv_kernel() {
    int b  = blockIdx.z;
    int m0 = blockIdx.y * 128;   // sq
    int n0 = blockIdx.x * 128;   // c
    int L  = (m0 / NHW + 1) * NHW;
    const int nIt = L / KSLAB;

    const __nv_bfloat16* P = g_p + (size_t)b * SS * SS;
    const __nv_bfloat16* V = g_v + (size_t)b * CC * SS;
    GEMM_VARS
    uint32_t tbA = sbase, tbB = sbase + STAGES * SZ_MK;

    for (int s = 0; s < STAGES - 1; s++) {
        stageMK(tbA + s * SZ_MK, P, SS, m0, s * KSLAB, tid);
        stageMK(tbB + s * SZ_MK, V, SS, n0, s * KSLAB, tid);
        cp_commit();
    }
    for (int i = 0; i < nIt; i++) {
        cp_wait<STAGES - 2>();
        __syncthreads();
        int sl = i % STAGES;
        SLAB_COMPUTE(fragA_MK, fragB_MK, tbA + sl * SZ_MK, tbB + sl * SZ_MK);
        int pf = i + STAGES - 1;
        if (pf < nIt) {
            int ps = pf % STAGES;
            stageMK(tbA + ps * SZ_MK, P, SS, m0, pf * KSLAB, tid);
            stageMK(tbB + ps * SZ_MK, V, SS, n0, pf * KSLAB, tid);
            cp_commit();
        }
    }

    __nv_bfloat16* O = g_o + (size_t)b * SS * CC;
#pragma unroll
    for (int mt = 0; mt < 4; mt++) {
        int m = m0 + wm + mt * 16 + qr;
#pragma unroll
        for (int nt = 0; nt < 8; nt++) {
            int n = n0 + wn + nt * 8 + qc * 2;
            *(__nv_bfloat162*)&O[(size_t)m * CC + n] =
                __floats2bfloat162_rn(acc[mt][nt][0], acc[mt][nt][1]);
            *(__nv_bfloat162*)&O[(size_t)(m + 8) * CC + n] =
                __floats2bfloat162_rn(acc[mt][nt][2], acc[mt][nt][3]);
        }
    }
}

// ---------------------------------------------------------------------------
// O-proj + residual (fp32 out): A = wo (MK), B = g_o (MK rows s)
// ---------------------------------------------------------------------------
__global__ void __launch_bounds__(128) oproj_kernel(
    const float* __restrict__ bo, const float* __restrict__ x,
    float* __restrict__ out) {

    int b  = blockIdx.z;
    int m0 = blockIdx.y * 128;   // c_out
    int n0 = blockIdx.x * 128;   // s

    const __nv_bfloat16* W = g_w[3];
    const __nv_bfloat16* O = g_o + (size_t)b * SS * CC;
    GEMM_VARS
    uint32_t tbA = sbase, tbB = sbase + STAGES * SZ_MK;

    for (int s = 0; s < STAGES - 1; s++) {
        stageMK(tbA + s * SZ_MK, W, CC, m0, s * KSLAB, tid);
        stageMK(tbB + s * SZ_MK, O, CC, n0, s * KSLAB, tid);
        cp_commit();
    }
    const int nIt = CC / KSLAB;
    for (int i = 0; i < nIt; i++) {
        cp_wait<STAGES - 2>();
        __syncthreads();
        int sl = i % STAGES;
        SLAB_COMPUTE(fragA_MK, fragB_MK, tbA + sl * SZ_MK, tbB + sl * SZ_MK);
        int pf = i + STAGES - 1;
        if (pf < nIt) {
            int ps = pf % STAGES;
            stageMK(tbA + ps * SZ_MK, W, CC, m0, pf * KSLAB, tid);
            stageMK(tbB + ps * SZ_MK, O, CC, n0, pf * KSLAB, tid);
            cp_commit();
        }
    }

#pragma unroll
    for (int mt = 0; mt < 4; mt++) {
        int m = m0 + wm + mt * 16 + qr;
        float bi0 = bo[m], bi1 = bo[m + 8];
#pragma unroll
        for (int nt = 0; nt < 8; nt++) {
            int n = n0 + wn + nt * 8 + qc * 2;
            const float2 x0 = *(const float2*)&x[((size_t)b * CC + m) * SS + n];
            const float2 x1 = *(const float2*)&x[((size_t)b * CC + m + 8) * SS + n];
            float2 v0 = make_float2(acc[mt][nt][0] + bi0 + x0.x, acc[mt][nt][1] + bi0 + x0.y);
            float2 v1 = make_float2(acc[mt][nt][2] + bi1 + x1.x, acc[mt][nt][3] + bi1 + x1.y);
            *(float2*)&out[((size_t)b * CC + m) * SS + n]     = v0;
            *(float2*)&out[((size_t)b * CC + m + 8) * SS + n] = v1;
        }
    }
}

// ---------------------------------------------------------------------------
extern "C" void kernel_launch(void* const* d_in, const int* in_sizes, int n_in,
                              void* d_out, int out_size) {
    const float* x     = (const float*)d_in[0];
    const float* gamma = (const float*)d_in[1];
    const float* wq    = (const float*)d_in[2];
    const float* bq    = (const float*)d_in[3];
    const float* wk    = (const float*)d_in[4];
    const float* bk    = (const float*)d_in[5];
    const float* wv    = (const float*)d_in[6];
    const float* bv    = (const float*)d_in[7];
    const float* wo    = (const float*)d_in[8];
    const float* bo    = (const float*)d_in[9];
    float* out = (float*)d_out;

    static int attr_done = 0;
    if (!attr_done) {
        cudaFuncSetAttribute(qkv_kernel,  cudaFuncAttributeMaxDynamicSharedMemorySize, DYN_SMEM);
        cudaFuncSetAttribute(qk_kernel,   cudaFuncAttributeMaxDynamicSharedMemorySize, DYN_SMEM);
        cudaFuncSetAttribute(pv_kernel,   cudaFuncAttributeMaxDynamicSharedMemorySize, DYN_SMEM);
        cudaFuncSetAttribute(oproj_kernel, cudaFuncAttributeMaxDynamicSharedMemorySize, DYN_SMEM);
        attr_done = 1;
    }

    prep_w_kernel<<<dim3(CC * CC / 256, 4), 256>>>(wq, wk, wv, wo);
    rms_kernel<<<dim3(SS / 256, BB), 256>>>(x, gamma);
    qkv_kernel<<<dim3(SS / 128, CC / 128, BB * 3), 128, DYN_SMEM>>>(bq, bk, bv);
    qk_kernel<<<dim3(SS / 128, SS / 128, BB), 128, DYN_SMEM>>>();
    softmax_kernel<<<dim3(SS, BB), 256>>>();
    pv_kernel<<<dim3(CC / 128, SS / 128, BB), 128, DYN_SMEM>>>();
    oproj_kernel<<<dim3(SS / 128, CC / 128, BB), 128, DYN_SMEM>>>(bo, x, out);
}